// round 1
// baseline (speedup 1.0000x reference)
#include <cuda_runtime.h>

#define Bsz 4
#define S   2048
#define D   128
#define H   8
#define DK  16
#define BH  (Bsz*H)

// ---- scratch (no allocations allowed) ----
__device__ float g_Q[BH*S*DK];       // [b,h,s,k] 4 MB
__device__ float g_K[BH*S*DK];
__device__ float g_V[BH*S*DK];
__device__ float g_colsum[BH*S];     // softmax normalizer over QUERY dim, per key m
__device__ float g_head[Bsz*S*D];    // concat-head output [b,s,h*DK+v]

// ============================================================
// Kernel 1: Q/K/V projections.  x[B*S,128] @ W[h][128,16] for 3*8 combos.
// Block: 32 rows of x, 256 threads.
// ============================================================
__global__ void proj_kernel(const float* __restrict__ x,
                            const float* __restrict__ wq,
                            const float* __restrict__ wk,
                            const float* __restrict__ wv) {
    __shared__ float xs[32][128];   // 16 KB
    __shared__ float ws[128][DK];   // 8 KB
    const int t = threadIdx.x;
    const int row0 = blockIdx.x * 32;          // global row in [0, B*S)

    for (int i = t; i < 32*128; i += 256) {
        int r = i >> 7, c = i & 127;
        xs[r][c] = x[(row0 + r) * D + c];
    }

    for (int combo = 0; combo < 24; combo++) {
        const int pj = combo >> 3, h = combo & 7;
        const float* W = (pj == 0 ? wq : pj == 1 ? wk : wv) + h * D * DK;
        __syncthreads();                        // guards xs (1st iter) / ws reuse
        for (int i = t; i < D*DK; i += 256) ws[i >> 4][i & 15] = W[i];
        __syncthreads();

        #pragma unroll
        for (int j = 0; j < 2; j++) {
            int o = t + j*256;                  // 512 outputs = 32 rows x 16 cols
            int r = o >> 4, c = o & 15;
            float acc = 0.f;
            #pragma unroll
            for (int d = 0; d < D; d++) acc += xs[r][d] * ws[d][c];
            int grow = row0 + r;                // = b*S + s
            int b = grow >> 11, s = grow & (S-1);
            float* dst = (pj == 0 ? g_Q : pj == 1 ? g_K : g_V);
            dst[((b*H + h)*S + s)*DK + c] = acc;
        }
    }
}

// ============================================================
// Kernel 2: colsum[m] = sum_q exp(0.25 * Q[q]·K[m])   (softmax over q!)
// Grid: (S/128 m-tiles, BH).  256 threads; thread -> column c = t%128,
// covers q rows t/128, t/128+2, ...
// ============================================================
__global__ void colsum_kernel() {
    __shared__ float Ks[128][17];   // pad 17: stride coprime with 32 banks
    __shared__ float Qs[128][17];
    __shared__ float red[128];
    const int t  = threadIdx.x;
    const int bh = blockIdx.y;
    const int m0 = blockIdx.x * 128;

    const float* Kbase = g_K + (bh*S + m0)*DK;
    for (int i = t; i < 128*DK; i += 256) Ks[i >> 4][i & 15] = Kbase[i];

    const int c = t & 127, ro = t >> 7;
    float acc = 0.f;
    const float* Qbh = g_Q + bh*S*DK;

    for (int q0 = 0; q0 < S; q0 += 128) {
        __syncthreads();                         // guards Ks (1st) / Qs reuse
        for (int i = t; i < 128*DK; i += 256) Qs[i >> 4][i & 15] = Qbh[q0*DK + i];
        __syncthreads();
        for (int qq = ro; qq < 128; qq += 2) {
            float sc = 0.f;
            #pragma unroll
            for (int j = 0; j < DK; j++) sc += Qs[qq][j] * Ks[c][j];
            acc += __expf(0.25f * sc);
        }
    }
    if (ro == 0) red[c] = acc;
    __syncthreads();
    if (ro == 1) g_colsum[bh*S + m0 + c] = red[c] + acc;
}

// ============================================================
// Kernel 3: out[q,:] = sum_m exp(0.25*Q[q]·K[m]) * (V[m,:]/colsum[m])
// Grid: (S/64 q-tiles, BH).  256 threads.
// Per m-chunk (64): phase1 builds E tile in SMEM (no duplicate exp work),
// phase2 is a tiny GEMM E[64,64] @ V'[64,16] into registers.
// ============================================================
__global__ void attn_out_kernel() {
    __shared__ float Qs[64][17];
    __shared__ float Ks[64][17];
    __shared__ float Vs[64][17];
    __shared__ float Es[64][68];    // pad 68 (%32==4) -> conflict-free reads
    const int t  = threadIdx.x;
    const int bh = blockIdx.y;
    const int q0 = blockIdx.x * 64;

    const float* Qbase = g_Q + (bh*S + q0)*DK;
    for (int i = t; i < 64*DK; i += 256) Qs[i >> 4][i & 15] = Qbase[i];

    float acc0 = 0.f, acc1 = 0.f, acc2 = 0.f, acc3 = 0.f;
    const int qrow = t >> 2;             // 0..63
    const int vg   = (t & 3) * 4;        // 0,4,8,12

    const float* Kbh  = g_K + bh*S*DK;
    const float* Vbh  = g_V + bh*S*DK;
    const float* csbh = g_colsum + bh*S;

    for (int m0 = 0; m0 < S; m0 += 64) {
        __syncthreads();                 // guards Qs (1st) / Ks,Vs,Es reuse
        for (int i = t; i < 64*DK; i += 256) {
            int r = i >> 4, cc = i & 15;
            Ks[r][cc] = Kbh[(m0 + r)*DK + cc];
            Vs[r][cc] = __fdividef(Vbh[(m0 + r)*DK + cc], csbh[m0 + r]);
        }
        __syncthreads();

        // phase 1: E tile
        for (int i = t; i < 64*64; i += 256) {
            int qq = i >> 6, mm = i & 63;
            float sc = 0.f;
            #pragma unroll
            for (int j = 0; j < DK; j++) sc += Qs[qq][j] * Ks[mm][j];
            Es[qq][mm] = __expf(0.25f * sc);
        }
        __syncthreads();

        // phase 2: out-tile accumulate
        #pragma unroll 8
        for (int mm = 0; mm < 64; mm++) {
            float e = Es[qrow][mm];
            acc0 += e * Vs[mm][vg + 0];
            acc1 += e * Vs[mm][vg + 1];
            acc2 += e * Vs[mm][vg + 2];
            acc3 += e * Vs[mm][vg + 3];
        }
    }

    const int b = bh >> 3, h = bh & 7;
    float* dst = g_head + (b*S + q0 + qrow)*D + h*DK + vg;
    dst[0] = acc0; dst[1] = acc1; dst[2] = acc2; dst[3] = acc3;
}

// ============================================================
// Kernel 4: out = head[B*S,128] @ w_o[128,128]
// Block: 64 rows, 256 threads; thread owns column c and 32 rows in regs.
// ============================================================
__global__ void final_proj_kernel(const float* __restrict__ wo,
                                  float* __restrict__ out) {
    __shared__ float hs[64][128];   // 32 KB
    const int t = threadIdx.x;
    const int row0 = blockIdx.x * 64;

    for (int i = t; i < 64*128; i += 256) hs[i >> 7][i & 127] = g_head[row0*D + i];
    __syncthreads();

    const int col = t & 127, rbase = t >> 7;   // rbase 0/1
    float acc[32];
    #pragma unroll
    for (int k = 0; k < 32; k++) acc[k] = 0.f;

    for (int j = 0; j < 128; j++) {
        float w = wo[j*D + col];               // coalesced, L1/L2-resident
        #pragma unroll
        for (int k = 0; k < 32; k++)
            acc[k] += hs[rbase + 2*k][j] * w;  // broadcast LDS
    }
    #pragma unroll
    for (int k = 0; k < 32; k++)
        out[(row0 + rbase + 2*k)*D + col] = acc[k];
}

// ============================================================
extern "C" void kernel_launch(void* const* d_in, const int* in_sizes, int n_in,
                              void* d_out, int out_size) {
    const float* x  = (const float*)d_in[0];
    const float* wq = (const float*)d_in[1];
    const float* wk = (const float*)d_in[2];
    const float* wv = (const float*)d_in[3];
    const float* wo = (const float*)d_in[4];
    float* out = (float*)d_out;

    proj_kernel     <<< Bsz*S/32, 256 >>>(x, wq, wk, wv);
    colsum_kernel   <<< dim3(S/128, BH), 256 >>>();
    attn_out_kernel <<< dim3(S/64,  BH), 256 >>>();
    final_proj_kernel<<< Bsz*S/64, 256 >>>(wo, out);
}

// round 2
// speedup vs baseline: 1.0243x; 1.0243x over previous
#include <cuda_runtime.h>

#define Bsz 4
#define S   2048
#define D   128
#define H   8
#define DK  16
#define BH  (Bsz*H)

typedef unsigned long long u64;

// ---- scratch (no device allocations allowed) ----
__device__ float g_Q[BH*S*DK];
__device__ float g_K[BH*S*DK];
__device__ float g_V[BH*S*DK];
__device__ float g_colsum[BH*S];
__device__ float g_head[Bsz*S*D];

// ---- packed fp32x2 helpers (SASS FFMA2 path) ----
__device__ __forceinline__ void ffma2(u64& d, u64 a, u64 b){
    asm("fma.rn.f32x2 %0, %1, %2, %0;" : "+l"(d) : "l"(a), "l"(b));
}
__device__ __forceinline__ u64 dup2(float x){
    u64 r; asm("mov.b64 %0, {%1, %1};" : "=l"(r) : "f"(x)); return r;
}
__device__ __forceinline__ float hsum2(u64 v){
    float lo, hi; asm("mov.b64 {%0, %1}, %2;" : "=f"(lo), "=f"(hi) : "l"(v));
    return lo + hi;
}
__device__ __forceinline__ float2 unpk(u64 v){
    float2 r; asm("mov.b64 {%0, %1}, %2;" : "=f"(r.x), "=f"(r.y) : "l"(v));
    return r;
}
__device__ __forceinline__ u64 lds64(const float* p){
    return *reinterpret_cast<const u64*>(p);
}
__device__ __forceinline__ u64 ldg64(const float* p){
    return *reinterpret_cast<const u64*>(p);
}

// ============================================================
// Kernel 1: Q/K/V projections. grid (B*S/64, 3), 128 threads.
// x tile transposed-free in smem; W transposed for paired-d LDS.64.
// ============================================================
__global__ void proj_kernel(const float* __restrict__ x,
                            const float* __restrict__ wq,
                            const float* __restrict__ wk,
                            const float* __restrict__ wv) {
    __shared__ float xs[64][132];    // pad 132: 16B-aligned rows, conflict-light
    __shared__ float wsT[16][132];   // [c][d]
    const int t = threadIdx.x;       // 128
    const int row0 = blockIdx.x * 64;
    const int pj = blockIdx.y;
    const float* W0 = (pj == 0 ? wq : pj == 1 ? wk : wv);
    float* dst = (pj == 0 ? g_Q : pj == 1 ? g_K : g_V);

    #pragma unroll
    for (int k = 0; k < 16; k++) {
        int idx = t + k*128;              // 2048 float4s
        int r = idx >> 5, q4 = idx & 31;
        *reinterpret_cast<float4*>(&xs[r][q4*4]) =
            *reinterpret_cast<const float4*>(x + (row0 + r)*D + q4*4);
    }

    const int rg = t >> 3, cg = t & 7;    // 4 rows x cols {cg, cg+8}
    for (int h = 0; h < H; h++) {
        __syncthreads();                  // wsT reuse / xs ready
        #pragma unroll
        for (int k = 0; k < 4; k++) {
            int idx = t + k*128;          // 512 float4s
            int d = idx >> 2, c4 = idx & 3;
            float4 v = *reinterpret_cast<const float4*>(W0 + h*D*DK + d*DK + c4*4);
            wsT[c4*4+0][d] = v.x; wsT[c4*4+1][d] = v.y;
            wsT[c4*4+2][d] = v.z; wsT[c4*4+3][d] = v.w;
        }
        __syncthreads();

        u64 acc[4][2] = {};
        #pragma unroll 8
        for (int d = 0; d < D; d += 2) {
            u64 w0 = lds64(&wsT[cg][d]);
            u64 w1 = lds64(&wsT[cg+8][d]);
            #pragma unroll
            for (int i = 0; i < 4; i++) {
                u64 xv = lds64(&xs[rg*4+i][d]);
                ffma2(acc[i][0], xv, w0);
                ffma2(acc[i][1], xv, w1);
            }
        }
        #pragma unroll
        for (int i = 0; i < 4; i++) {
            int grow = row0 + rg*4 + i;
            int b = grow >> 11, s = grow & (S-1);
            float* o = dst + ((b*H + h)*S + s)*DK;
            o[cg]   = hsum2(acc[i][0]);
            o[cg+8] = hsum2(acc[i][1]);
        }
    }
}

// ============================================================
// Kernel 2: colsum[m] = sum_q exp(0.25*Q[q].K[m]).
// grid (S/512, BH), 256 threads; thread owns cols t, t+256; K in regs.
// ============================================================
__global__ void colsum_kernel() {
    __shared__ float Qs[64][16];
    const int t  = threadIdx.x;
    const int bh = blockIdx.y;
    const int c0 = blockIdx.x*512 + t;
    const float* Kb = g_K + bh*S*DK;
    const float* Qb = g_Q + bh*S*DK;

    u64 k0[8], k1[8];
    #pragma unroll
    for (int j = 0; j < 8; j++) {
        k0[j] = ldg64(Kb + c0*DK + 2*j);
        k1[j] = ldg64(Kb + (c0+256)*DK + 2*j);
    }

    float s0 = 0.f, s1 = 0.f;
    for (int q0 = 0; q0 < S; q0 += 64) {
        __syncthreads();
        {
            int r = t >> 2, q4 = t & 3;   // 256 float4s = whole tile
            *reinterpret_cast<float4*>(&Qs[r][q4*4]) =
                *reinterpret_cast<const float4*>(Qb + (q0 + r)*DK + q4*4);
        }
        __syncthreads();
        #pragma unroll 4
        for (int qq = 0; qq < 64; qq++) {
            u64 a0 = 0, a1 = 0;
            #pragma unroll
            for (int j = 0; j < 8; j++) {
                u64 qv = lds64(&Qs[qq][2*j]);   // broadcast
                ffma2(a0, qv, k0[j]);
                ffma2(a1, qv, k1[j]);
            }
            s0 += __expf(0.25f * hsum2(a0));
            s1 += __expf(0.25f * hsum2(a1));
        }
    }
    g_colsum[bh*S + c0]       = s0;
    g_colsum[bh*S + c0 + 256] = s1;
}

// ============================================================
// Kernel 3: out[q,:] = sum_m E[q,m] * (V[m,:]/colsum[m]).
// grid (S/128, BH), 256 threads. E tile stored m-major [64][132].
// Phase2: 8q x 4v thread tile, m-split 4 with final smem reduction.
// ============================================================
__global__ void attn_kernel() {
    __shared__ float Qs[128][16];
    __shared__ float Es[64][132];   // [m][q]; 132 -> 16B aligned rows
    __shared__ float Vs[64][16];    // V / colsum
    const int t  = threadIdx.x;
    const int bh = blockIdx.y;
    const int q0 = blockIdx.x * 128;
    const float* Qb = g_Q + (bh*S + q0)*DK;
    const float* Kb = g_K + bh*S*DK;
    const float* Vb = g_V + bh*S*DK;
    const float* cs = g_colsum + bh*S;

    #pragma unroll
    for (int k = 0; k < 2; k++) {
        int idx = t + k*256;              // 512 float4s
        int r = idx >> 2, q4 = idx & 3;
        *reinterpret_cast<float4*>(&Qs[r][q4*4]) =
            *reinterpret_cast<const float4*>(Qb + r*DK + q4*4);
    }

    // phase-1 ids: column pair {cg, cg+32}, q rows qg*16 + rotated i
    const int cg = t & 31, qg = t >> 5;
    // phase-2 ids: m-group, 8 q-rows, 4 v-cols
    const int mg  = t >> 6;
    const int qg2 = (t >> 2) & 15;
    const int vg  = t & 3;

    u64 acc[8][2] = {};                   // 8 q-rows x 2 v-pairs
    __syncthreads();                      // Qs ready

    for (int m0 = 0; m0 < S; m0 += 64) {
        // K columns for this chunk, packed pairs in regs (L2-resident)
        u64 kr0[8], kr1[8];
        #pragma unroll
        for (int j = 0; j < 8; j++) {
            kr0[j] = ldg64(Kb + (m0 + cg)*DK + 2*j);
            kr1[j] = ldg64(Kb + (m0 + cg + 32)*DK + 2*j);
        }
        // stage V' = V / colsum (1 float4 per thread)
        {
            int r = t >> 2, v4 = t & 3;
            float4 v = *reinterpret_cast<const float4*>(Vb + (m0 + r)*DK + v4*4);
            float inv = __frcp_rn(cs[m0 + r]);
            v.x *= inv; v.y *= inv; v.z *= inv; v.w *= inv;
            *reinterpret_cast<float4*>(&Vs[r][v4*4]) = v;
        }
        // phase 1: E tile (rotated q order de-conflicts STS)
        #pragma unroll 2
        for (int i = 0; i < 16; i++) {
            int qq = qg*16 + ((i + cg) & 15);
            u64 a0 = 0, a1 = 0;
            #pragma unroll
            for (int j = 0; j < 8; j++) {
                u64 qv = lds64(&Qs[qq][2*j]);   // broadcast
                ffma2(a0, qv, kr0[j]);
                ffma2(a1, qv, kr1[j]);
            }
            Es[cg][qq]      = __expf(0.25f * hsum2(a0));
            Es[cg + 32][qq] = __expf(0.25f * hsum2(a1));
        }
        __syncthreads();
        // phase 2: acc += E[mm, q-tile]^T outer V'[mm, v-tile]
        #pragma unroll 4
        for (int mi = 0; mi < 16; mi++) {
            int mm = mg*16 + mi;
            float4 e0 = *reinterpret_cast<const float4*>(&Es[mm][qg2*8]);
            float4 e1 = *reinterpret_cast<const float4*>(&Es[mm][qg2*8 + 4]);
            u64 v0 = lds64(&Vs[mm][vg*4]);
            u64 v1 = lds64(&Vs[mm][vg*4 + 2]);
            u64 e;
            e = dup2(e0.x); ffma2(acc[0][0], e, v0); ffma2(acc[0][1], e, v1);
            e = dup2(e0.y); ffma2(acc[1][0], e, v0); ffma2(acc[1][1], e, v1);
            e = dup2(e0.z); ffma2(acc[2][0], e, v0); ffma2(acc[2][1], e, v1);
            e = dup2(e0.w); ffma2(acc[3][0], e, v0); ffma2(acc[3][1], e, v1);
            e = dup2(e1.x); ffma2(acc[4][0], e, v0); ffma2(acc[4][1], e, v1);
            e = dup2(e1.y); ffma2(acc[5][0], e, v0); ffma2(acc[5][1], e, v1);
            e = dup2(e1.z); ffma2(acc[6][0], e, v0); ffma2(acc[6][1], e, v1);
            e = dup2(e1.w); ffma2(acc[7][0], e, v0); ffma2(acc[7][1], e, v1);
        }
        __syncthreads();                  // Es/Vs reuse next chunk
    }

    // cross-mg reduction (reuse Es smem: 3 slabs of 2048 floats)
    float* red = &Es[0][0];
    if (mg) {
        float* slab = red + (mg - 1)*2048;
        #pragma unroll
        for (int i = 0; i < 8; i++) {
            int e0 = (qg2*8 + i)*16 + vg*4;
            float2 p0 = unpk(acc[i][0]), p1 = unpk(acc[i][1]);
            slab[e0+0] = p0.x; slab[e0+1] = p0.y;
            slab[e0+2] = p1.x; slab[e0+3] = p1.y;
        }
    }
    __syncthreads();
    if (mg == 0) {
        const int b = bh >> 3, h = bh & 7;
        #pragma unroll
        for (int i = 0; i < 8; i++) {
            int r = qg2*8 + i;
            int e0 = r*16 + vg*4;
            float2 p0 = unpk(acc[i][0]), p1 = unpk(acc[i][1]);
            float4 o;
            o.x = p0.x + red[e0+0] + red[2048+e0+0] + red[4096+e0+0];
            o.y = p0.y + red[e0+1] + red[2048+e0+1] + red[4096+e0+1];
            o.z = p1.x + red[e0+2] + red[2048+e0+2] + red[4096+e0+2];
            o.w = p1.y + red[e0+3] + red[2048+e0+3] + red[4096+e0+3];
            *reinterpret_cast<float4*>(g_head + (b*S + q0 + r)*D + h*DK + vg*4) = o;
        }
    }
}

// ============================================================
// Kernel 4: out = head[B*S,128] @ w_o[128,128]. grid 256, 256 thr.
// head tile transposed in smem -> paired-row LDS.64, broadcast.
// ============================================================
__global__ void final_proj_kernel(const float* __restrict__ wo,
                                  float* __restrict__ out) {
    __shared__ float hsT[128][34];   // [j][row]
    const int t = threadIdx.x;
    const int row0 = blockIdx.x * 32;

    #pragma unroll
    for (int k = 0; k < 4; k++) {
        int idx = t + k*256;             // 1024 float4s
        int r = idx >> 5, j4 = idx & 31;
        float4 v = *reinterpret_cast<const float4*>(g_head + (row0 + r)*D + j4*4);
        hsT[j4*4+0][r] = v.x; hsT[j4*4+1][r] = v.y;
        hsT[j4*4+2][r] = v.z; hsT[j4*4+3][r] = v.w;
    }
    __syncthreads();

    const int c = t & 127, rh = t >> 7;  // col + 16-row half
    u64 acc[8] = {};
    #pragma unroll 4
    for (int j = 0; j < D; j++) {
        u64 w = dup2(wo[j*D + c]);       // L1/L2-hot, coalesced
        #pragma unroll
        for (int p = 0; p < 8; p++)
            ffma2(acc[p], lds64(&hsT[j][rh*16 + 2*p]), w);   // broadcast
    }
    #pragma unroll
    for (int p = 0; p < 8; p++) {
        float2 v = unpk(acc[p]);
        int r = row0 + rh*16 + 2*p;
        out[r*D + c]       = v.x;
        out[(r+1)*D + c]   = v.y;
    }
}

// ============================================================
extern "C" void kernel_launch(void* const* d_in, const int* in_sizes, int n_in,
                              void* d_out, int out_size) {
    const float* x  = (const float*)d_in[0];
    const float* wq = (const float*)d_in[1];
    const float* wk = (const float*)d_in[2];
    const float* wv = (const float*)d_in[3];
    const float* wo = (const float*)d_in[4];
    float* out = (float*)d_out;

    proj_kernel      <<< dim3(Bsz*S/64, 3), 128 >>>(x, wq, wk, wv);
    colsum_kernel    <<< dim3(S/512, BH),   256 >>>();
    attn_kernel      <<< dim3(S/128, BH),   256 >>>();
    final_proj_kernel<<< Bsz*S/32,          256 >>>(wo, out);
}

// round 3
// speedup vs baseline: 2.3743x; 2.3180x over previous
#include <cuda_runtime.h>

#define Bsz 4
#define S   2048
#define D   128
#define H   8
#define DK  16
#define BH  (Bsz*H)

#define QT  64      // q rows per attn CTA
#define MC  128     // m rows staged per chunk

typedef unsigned long long u64;

// 0.25 * log2(e): folded into Q at projection time so attention uses raw ex2
#define SCQ 0.36067376022224086f

// ---- scratch (no device allocations allowed) ----
__device__ float g_Q[BH*S*DK];       // pre-scaled by SCQ
__device__ float g_K[BH*S*DK];
__device__ float g_V[BH*S*DK];
__device__ float g_colsum[BH*S];
__device__ float g_head[Bsz*S*D];

// ---- packed fp32x2 helpers ----
__device__ __forceinline__ void ffma2(u64& d, u64 a, u64 b){
    asm("fma.rn.f32x2 %0, %1, %2, %0;" : "+l"(d) : "l"(a), "l"(b));
}
__device__ __forceinline__ u64 dup2(float x){
    u64 r; asm("mov.b64 %0, {%1, %1};" : "=l"(r) : "f"(x)); return r;
}
__device__ __forceinline__ float hsum2(u64 v){
    float lo, hi; asm("mov.b64 {%0, %1}, %2;" : "=f"(lo), "=f"(hi) : "l"(v));
    return lo + hi;
}
__device__ __forceinline__ float2 unpk(u64 v){
    float2 r; asm("mov.b64 {%0, %1}, %2;" : "=f"(r.x), "=f"(r.y) : "l"(v));
    return r;
}
__device__ __forceinline__ float ex2f(float x){
    float r; asm("ex2.approx.f32 %0, %1;" : "=f"(r) : "f"(x)); return r;
}
__device__ __forceinline__ u64 lds64(const float* p){
    return *reinterpret_cast<const u64*>(p);
}
__device__ __forceinline__ u64 ldg64(const float* p){
    return *reinterpret_cast<const u64*>(p);
}

// ============================================================
// Kernel 1: Q/K/V projections. grid (B*S/64, 3), 128 threads.
// Q outputs are pre-scaled by SCQ = 0.25*log2(e).
// ============================================================
__global__ void proj_kernel(const float* __restrict__ x,
                            const float* __restrict__ wq,
                            const float* __restrict__ wk,
                            const float* __restrict__ wv) {
    __shared__ float xs[64][132];
    __shared__ float wsT[16][132];
    const int t = threadIdx.x;       // 128
    const int row0 = blockIdx.x * 64;
    const int pj = blockIdx.y;
    const float* W0 = (pj == 0 ? wq : pj == 1 ? wk : wv);
    float* dst = (pj == 0 ? g_Q : pj == 1 ? g_K : g_V);
    const float oscale = (pj == 0) ? SCQ : 1.0f;

    #pragma unroll
    for (int k = 0; k < 16; k++) {
        int idx = t + k*128;
        int r = idx >> 5, q4 = idx & 31;
        *reinterpret_cast<float4*>(&xs[r][q4*4]) =
            *reinterpret_cast<const float4*>(x + (row0 + r)*D + q4*4);
    }

    const int rg = t >> 3, cg = t & 7;
    for (int h = 0; h < H; h++) {
        __syncthreads();
        #pragma unroll
        for (int k = 0; k < 4; k++) {
            int idx = t + k*128;
            int d = idx >> 2, c4 = idx & 3;
            float4 v = *reinterpret_cast<const float4*>(W0 + h*D*DK + d*DK + c4*4);
            wsT[c4*4+0][d] = v.x; wsT[c4*4+1][d] = v.y;
            wsT[c4*4+2][d] = v.z; wsT[c4*4+3][d] = v.w;
        }
        __syncthreads();

        u64 acc[4][2] = {};
        #pragma unroll 8
        for (int d = 0; d < D; d += 2) {
            u64 w0 = lds64(&wsT[cg][d]);
            u64 w1 = lds64(&wsT[cg+8][d]);
            #pragma unroll
            for (int i = 0; i < 4; i++) {
                u64 xv = lds64(&xs[rg*4+i][d]);
                ffma2(acc[i][0], xv, w0);
                ffma2(acc[i][1], xv, w1);
            }
        }
        #pragma unroll
        for (int i = 0; i < 4; i++) {
            int grow = row0 + rg*4 + i;
            int b = grow >> 11, s = grow & (S-1);
            float* o = dst + ((b*H + h)*S + s)*DK;
            o[cg]   = hsum2(acc[i][0]) * oscale;
            o[cg+8] = hsum2(acc[i][1]) * oscale;
        }
    }
}

// ============================================================
// Kernel 2: colsum[m] = sum_q ex2(Qhat[q].K[m])  (softmax over q)
// grid (S/128, BH) = 512 CTAs, 128 threads, 1 m-column per thread.
// K column in registers; Q rows broadcast from SMEM.
// ============================================================
__global__ void __launch_bounds__(128) colsum_kernel() {
    __shared__ float Qs[128][16];
    const int t  = threadIdx.x;
    const int bh = blockIdx.y;
    const int m  = blockIdx.x*128 + t;
    const float* Kb = g_K + bh*S*DK;
    const float* Qb = g_Q + bh*S*DK;

    u64 k[8];
    #pragma unroll
    for (int j = 0; j < 8; j++) k[j] = ldg64(Kb + m*DK + 2*j);

    float s = 0.f;
    for (int q0 = 0; q0 < S; q0 += 128) {
        __syncthreads();
        #pragma unroll
        for (int i = 0; i < 4; i++) {
            int idx = t + i*128;                  // 512 float4s
            int r = idx >> 2, q4 = idx & 3;
            *reinterpret_cast<float4*>(&Qs[r][q4*4]) =
                *reinterpret_cast<const float4*>(Qb + (q0 + r)*DK + q4*4);
        }
        __syncthreads();
        #pragma unroll 4
        for (int qq = 0; qq < 128; qq++) {
            u64 a = 0;
            #pragma unroll
            for (int j = 0; j < 8; j++)
                ffma2(a, lds64(&Qs[qq][2*j]), k[j]);   // broadcast
            s += ex2f(hsum2(a));
        }
    }
    g_colsum[bh*S + m] = s;
}

// ============================================================
// Kernel 3: out[q,:] = sum_m ex2(Qhat[q].K[m]) * (V[m,:]/colsum[m])
// grid (S/QT, BH) = 1024 CTAs, 128 threads (4 warps).
// Lane owns q rows {lane, lane+32} + their 16-wide accumulators in regs.
// Warps split m; K/V' broadcast from SMEM; one reduction at the end.
// ============================================================
__global__ void __launch_bounds__(128) attn_kernel() {
    __shared__ float Ks[MC][16];
    __shared__ float Vs[MC][16];
    __shared__ float red[3][QT][18];   // padded rows: conflict-light
    const int t    = threadIdx.x;
    const int w    = t >> 5, lane = t & 31;
    const int bh   = blockIdx.y;
    const int q0   = blockIdx.x * QT;
    const float* Qb = g_Q + (bh*S + q0)*DK;
    const float* Kb = g_K + bh*S*DK;
    const float* Vb = g_V + bh*S*DK;
    const float* cs = g_colsum + bh*S;

    u64 qa[8], qb[8];
    #pragma unroll
    for (int j = 0; j < 8; j++) {
        qa[j] = ldg64(Qb + lane*DK + 2*j);
        qb[j] = ldg64(Qb + (lane+32)*DK + 2*j);
    }
    u64 acc0[8] = {}, acc1[8] = {};

    for (int m0 = 0; m0 < S; m0 += MC) {
        __syncthreads();
        #pragma unroll
        for (int i = 0; i < 4; i++) {
            int idx = t + i*128;                  // 512 float4s each for K and V
            int r = idx >> 2, c4 = idx & 3;
            *reinterpret_cast<float4*>(&Ks[r][c4*4]) =
                *reinterpret_cast<const float4*>(Kb + (m0 + r)*DK + c4*4);
            float4 v = *reinterpret_cast<const float4*>(Vb + (m0 + r)*DK + c4*4);
            float inv = __frcp_rn(cs[m0 + r]);
            v.x *= inv; v.y *= inv; v.z *= inv; v.w *= inv;
            *reinterpret_cast<float4*>(&Vs[r][c4*4]) = v;
        }
        __syncthreads();

        const int mbase = w * 32;
        #pragma unroll 4
        for (int mi = 0; mi < 32; mi++) {
            int m = mbase + mi;
            u64 kk[8];
            #pragma unroll
            for (int j = 0; j < 8; j++) kk[j] = lds64(&Ks[m][2*j]);  // broadcast
            u64 a0 = 0, a1 = 0;
            #pragma unroll
            for (int j = 0; j < 8; j++) {
                ffma2(a0, qa[j], kk[j]);
                ffma2(a1, qb[j], kk[j]);
            }
            float e0 = ex2f(hsum2(a0));
            float e1 = ex2f(hsum2(a1));
            u64 vv[8];
            #pragma unroll
            for (int j = 0; j < 8; j++) vv[j] = lds64(&Vs[m][2*j]);  // broadcast
            u64 E0 = dup2(e0), E1 = dup2(e1);
            #pragma unroll
            for (int j = 0; j < 8; j++) {
                ffma2(acc0[j], E0, vv[j]);
                ffma2(acc1[j], E1, vv[j]);
            }
        }
    }

    // cross-warp reduction over the 4 m-slices
    __syncthreads();
    if (w) {
        #pragma unroll
        for (int j = 0; j < 8; j++) {
            float2 p0 = unpk(acc0[j]), p1 = unpk(acc1[j]);
            red[w-1][lane][2*j]        = p0.x;
            red[w-1][lane][2*j+1]      = p0.y;
            red[w-1][lane+32][2*j]     = p1.x;
            red[w-1][lane+32][2*j+1]   = p1.y;
        }
    }
    __syncthreads();
    if (w == 0) {
        const int b = bh >> 3, h = bh & 7;
        float o0[16], o1[16];
        #pragma unroll
        for (int j = 0; j < 8; j++) {
            float2 p0 = unpk(acc0[j]), p1 = unpk(acc1[j]);
            o0[2*j] = p0.x; o0[2*j+1] = p0.y;
            o1[2*j] = p1.x; o1[2*j+1] = p1.y;
        }
        #pragma unroll
        for (int sl = 0; sl < 3; sl++) {
            #pragma unroll
            for (int c = 0; c < 16; c++) {
                o0[c] += red[sl][lane][c];
                o1[c] += red[sl][lane+32][c];
            }
        }
        float* d0 = g_head + (b*S + q0 + lane)*D      + h*DK;
        float* d1 = g_head + (b*S + q0 + lane + 32)*D + h*DK;
        #pragma unroll
        for (int c4 = 0; c4 < 4; c4++) {
            *reinterpret_cast<float4*>(d0 + c4*4) =
                make_float4(o0[c4*4], o0[c4*4+1], o0[c4*4+2], o0[c4*4+3]);
            *reinterpret_cast<float4*>(d1 + c4*4) =
                make_float4(o1[c4*4], o1[c4*4+1], o1[c4*4+2], o1[c4*4+3]);
        }
    }
}

// ============================================================
// Kernel 4: out = head[B*S,128] @ w_o[128,128]. grid 256, 256 thr.
// ============================================================
__global__ void final_proj_kernel(const float* __restrict__ wo,
                                  float* __restrict__ out) {
    __shared__ float hsT[128][34];
    const int t = threadIdx.x;
    const int row0 = blockIdx.x * 32;

    #pragma unroll
    for (int k = 0; k < 4; k++) {
        int idx = t + k*256;
        int r = idx >> 5, j4 = idx & 31;
        float4 v = *reinterpret_cast<const float4*>(g_head + (row0 + r)*D + j4*4);
        hsT[j4*4+0][r] = v.x; hsT[j4*4+1][r] = v.y;
        hsT[j4*4+2][r] = v.z; hsT[j4*4+3][r] = v.w;
    }
    __syncthreads();

    const int c = t & 127, rh = t >> 7;
    u64 acc[8] = {};
    #pragma unroll 4
    for (int j = 0; j < D; j++) {
        u64 w = dup2(wo[j*D + c]);
        #pragma unroll
        for (int p = 0; p < 8; p++)
            ffma2(acc[p], lds64(&hsT[j][rh*16 + 2*p]), w);
    }
    #pragma unroll
    for (int p = 0; p < 8; p++) {
        float2 v = unpk(acc[p]);
        int r = row0 + rh*16 + 2*p;
        out[r*D + c]     = v.x;
        out[(r+1)*D + c] = v.y;
    }
}

// ============================================================
extern "C" void kernel_launch(void* const* d_in, const int* in_sizes, int n_in,
                              void* d_out, int out_size) {
    const float* x  = (const float*)d_in[0];
    const float* wq = (const float*)d_in[1];
    const float* wk = (const float*)d_in[2];
    const float* wv = (const float*)d_in[3];
    const float* wo = (const float*)d_in[4];
    float* out = (float*)d_out;

    proj_kernel      <<< dim3(Bsz*S/64, 3), 128 >>>(x, wq, wk, wv);
    colsum_kernel    <<< dim3(S/128, BH),   128 >>>();
    attn_kernel      <<< dim3(S/QT, BH),    128 >>>();
    final_proj_kernel<<< Bsz*S/32,          256 >>>(wo, out);
}

// round 4
// speedup vs baseline: 2.4004x; 1.0110x over previous
#include <cuda_runtime.h>

#define Bsz 4
#define S   2048
#define D   128
#define H   8
#define DK  16
#define BH  (Bsz*H)

#define QT  64      // q rows per attn CTA
#define MC  128     // m rows staged per chunk

typedef unsigned long long u64;

// 0.25 * log2(e): folded into Q at projection time so attention uses raw ex2
#define SCQ 0.36067376022224086f

// ---- scratch (no device allocations allowed) ----
__device__ float g_Q[BH*S*DK];       // pre-scaled by SCQ
__device__ float g_K[BH*S*DK];
__device__ float g_V[BH*S*DK];
__device__ float g_colsum[BH*S];
__device__ float g_head[Bsz*S*D];

// ---- packed fp32x2 helpers ----
__device__ __forceinline__ void ffma2(u64& d, u64 a, u64 b){
    asm("fma.rn.f32x2 %0, %1, %2, %0;" : "+l"(d) : "l"(a), "l"(b));
}
__device__ __forceinline__ u64 dup2(float x){
    u64 r; asm("mov.b64 %0, {%1, %1};" : "=l"(r) : "f"(x)); return r;
}
__device__ __forceinline__ float hsum2(u64 v){
    float lo, hi; asm("mov.b64 {%0, %1}, %2;" : "=f"(lo), "=f"(hi) : "l"(v));
    return lo + hi;
}
__device__ __forceinline__ float2 unpk(u64 v){
    float2 r; asm("mov.b64 {%0, %1}, %2;" : "=f"(r.x), "=f"(r.y) : "l"(v));
    return r;
}
__device__ __forceinline__ float ex2f(float x){
    float r; asm("ex2.approx.f32 %0, %1;" : "=f"(r) : "f"(x)); return r;
}
__device__ __forceinline__ u64 lds64(const float* p){
    return *reinterpret_cast<const u64*>(p);
}
__device__ __forceinline__ u64 ldg64(const float* p){
    return *reinterpret_cast<const u64*>(p);
}

// ============================================================
// Kernel 1: Q/K/V projections. grid (B*S/64, 3), 128 threads.
// Q outputs are pre-scaled by SCQ = 0.25*log2(e).
// ============================================================
__global__ void proj_kernel(const float* __restrict__ x,
                            const float* __restrict__ wq,
                            const float* __restrict__ wk,
                            const float* __restrict__ wv) {
    __shared__ float xs[64][132];
    __shared__ float wsT[16][132];
    const int t = threadIdx.x;       // 128
    const int row0 = blockIdx.x * 64;
    const int pj = blockIdx.y;
    const float* W0 = (pj == 0 ? wq : pj == 1 ? wk : wv);
    float* dst = (pj == 0 ? g_Q : pj == 1 ? g_K : g_V);
    const float oscale = (pj == 0) ? SCQ : 1.0f;

    #pragma unroll
    for (int k = 0; k < 16; k++) {
        int idx = t + k*128;
        int r = idx >> 5, q4 = idx & 31;
        *reinterpret_cast<float4*>(&xs[r][q4*4]) =
            *reinterpret_cast<const float4*>(x + (row0 + r)*D + q4*4);
    }

    const int rg = t >> 3, cg = t & 7;
    for (int h = 0; h < H; h++) {
        __syncthreads();
        #pragma unroll
        for (int k = 0; k < 4; k++) {
            int idx = t + k*128;
            int d = idx >> 2, c4 = idx & 3;
            float4 v = *reinterpret_cast<const float4*>(W0 + h*D*DK + d*DK + c4*4);
            wsT[c4*4+0][d] = v.x; wsT[c4*4+1][d] = v.y;
            wsT[c4*4+2][d] = v.z; wsT[c4*4+3][d] = v.w;
        }
        __syncthreads();

        u64 acc[4][2] = {};
        #pragma unroll 8
        for (int d = 0; d < D; d += 2) {
            u64 w0 = lds64(&wsT[cg][d]);
            u64 w1 = lds64(&wsT[cg+8][d]);
            #pragma unroll
            for (int i = 0; i < 4; i++) {
                u64 xv = lds64(&xs[rg*4+i][d]);
                ffma2(acc[i][0], xv, w0);
                ffma2(acc[i][1], xv, w1);
            }
        }
        #pragma unroll
        for (int i = 0; i < 4; i++) {
            int grow = row0 + rg*4 + i;
            int b = grow >> 11, s = grow & (S-1);
            float* o = dst + ((b*H + h)*S + s)*DK;
            o[cg]   = hsum2(acc[i][0]) * oscale;
            o[cg+8] = hsum2(acc[i][1]) * oscale;
        }
    }
}

// ============================================================
// Kernel 2: colsum[m] = sum_q ex2(Qhat[q].K[m])  (softmax over q)
// grid (S/128, BH) = 512 CTAs, 128 threads, 1 m-column per thread.
// K column in registers; Q rows broadcast from SMEM via LDS.128.
// ============================================================
__global__ void __launch_bounds__(128) colsum_kernel() {
    __shared__ float Qs[128][16];
    const int t  = threadIdx.x;
    const int bh = blockIdx.y;
    const int m  = blockIdx.x*128 + t;
    const float* Kb = g_K + bh*S*DK;
    const float* Qb = g_Q + bh*S*DK;

    u64 k[8];
    #pragma unroll
    for (int j = 0; j < 8; j++) k[j] = ldg64(Kb + m*DK + 2*j);

    float s = 0.f;
    for (int q0 = 0; q0 < S; q0 += 128) {
        __syncthreads();
        #pragma unroll
        for (int i = 0; i < 4; i++) {
            int idx = t + i*128;                  // 512 float4s
            int r = idx >> 2, q4 = idx & 3;
            *reinterpret_cast<float4*>(&Qs[r][q4*4]) =
                *reinterpret_cast<const float4*>(Qb + (q0 + r)*DK + q4*4);
        }
        __syncthreads();
        #pragma unroll 4
        for (int qq = 0; qq < 128; qq++) {
            const ulonglong2* qp = reinterpret_cast<const ulonglong2*>(&Qs[qq][0]);
            u64 a = 0;
            #pragma unroll
            for (int p = 0; p < 4; p++) {
                ulonglong2 qv = qp[p];            // LDS.128 broadcast
                ffma2(a, qv.x, k[2*p]);
                ffma2(a, qv.y, k[2*p+1]);
            }
            s += ex2f(hsum2(a));
        }
    }
    g_colsum[bh*S + m] = s;
}

// ============================================================
// Kernel 3: out[q,:] = sum_m ex2(Qhat[q].K[m]) * (V[m,:]/colsum[m])
// grid (S/QT, BH) = 1024 CTAs, 128 threads (4 warps).
// Lane owns q rows {lane, lane+32}; warps split m; K/V' broadcast
// from SMEM via LDS.128 (2 u64 operands per load, zero repack).
// ============================================================
__global__ void __launch_bounds__(128) attn_kernel() {
    __shared__ float Ks[MC][16];
    __shared__ float Vs[MC][16];
    __shared__ float red[3][QT][18];
    const int t    = threadIdx.x;
    const int w    = t >> 5, lane = t & 31;
    const int bh   = blockIdx.y;
    const int q0   = blockIdx.x * QT;
    const float* Qb = g_Q + (bh*S + q0)*DK;
    const float* Kb = g_K + bh*S*DK;
    const float* Vb = g_V + bh*S*DK;
    const float* cs = g_colsum + bh*S;

    u64 qa[8], qb[8];
    #pragma unroll
    for (int j = 0; j < 8; j++) {
        qa[j] = ldg64(Qb + lane*DK + 2*j);
        qb[j] = ldg64(Qb + (lane+32)*DK + 2*j);
    }
    u64 acc0[8] = {}, acc1[8] = {};

    for (int m0 = 0; m0 < S; m0 += MC) {
        __syncthreads();
        #pragma unroll
        for (int i = 0; i < 4; i++) {
            int idx = t + i*128;                  // 512 float4s each for K and V
            int r = idx >> 2, c4 = idx & 3;
            *reinterpret_cast<float4*>(&Ks[r][c4*4]) =
                *reinterpret_cast<const float4*>(Kb + (m0 + r)*DK + c4*4);
            float4 v = *reinterpret_cast<const float4*>(Vb + (m0 + r)*DK + c4*4);
            float inv = __frcp_rn(cs[m0 + r]);
            v.x *= inv; v.y *= inv; v.z *= inv; v.w *= inv;
            *reinterpret_cast<float4*>(&Vs[r][c4*4]) = v;
        }
        __syncthreads();

        const int mbase = w * 32;
        #pragma unroll 4
        for (int mi = 0; mi < 32; mi++) {
            int m = mbase + mi;
            const ulonglong2* kp = reinterpret_cast<const ulonglong2*>(&Ks[m][0]);
            u64 a0 = 0, a1 = 0;
            #pragma unroll
            for (int p = 0; p < 4; p++) {
                ulonglong2 kv = kp[p];            // LDS.128 broadcast
                ffma2(a0, qa[2*p],   kv.x);
                ffma2(a0, qa[2*p+1], kv.y);
                ffma2(a1, qb[2*p],   kv.x);
                ffma2(a1, qb[2*p+1], kv.y);
            }
            u64 E0 = dup2(ex2f(hsum2(a0)));
            u64 E1 = dup2(ex2f(hsum2(a1)));
            const ulonglong2* vp = reinterpret_cast<const ulonglong2*>(&Vs[m][0]);
            #pragma unroll
            for (int p = 0; p < 4; p++) {
                ulonglong2 vv = vp[p];            // LDS.128 broadcast
                ffma2(acc0[2*p],   E0, vv.x);
                ffma2(acc0[2*p+1], E0, vv.y);
                ffma2(acc1[2*p],   E1, vv.x);
                ffma2(acc1[2*p+1], E1, vv.y);
            }
        }
    }

    // cross-warp reduction over the 4 m-slices
    __syncthreads();
    if (w) {
        #pragma unroll
        for (int j = 0; j < 8; j++) {
            float2 p0 = unpk(acc0[j]), p1 = unpk(acc1[j]);
            red[w-1][lane][2*j]        = p0.x;
            red[w-1][lane][2*j+1]      = p0.y;
            red[w-1][lane+32][2*j]     = p1.x;
            red[w-1][lane+32][2*j+1]   = p1.y;
        }
    }
    __syncthreads();
    if (w == 0) {
        const int b = bh >> 3, h = bh & 7;
        float o0[16], o1[16];
        #pragma unroll
        for (int j = 0; j < 8; j++) {
            float2 p0 = unpk(acc0[j]), p1 = unpk(acc1[j]);
            o0[2*j] = p0.x; o0[2*j+1] = p0.y;
            o1[2*j] = p1.x; o1[2*j+1] = p1.y;
        }
        #pragma unroll
        for (int sl = 0; sl < 3; sl++) {
            #pragma unroll
            for (int c = 0; c < 16; c++) {
                o0[c] += red[sl][lane][c];
                o1[c] += red[sl][lane+32][c];
            }
        }
        float* d0 = g_head + (b*S + q0 + lane)*D      + h*DK;
        float* d1 = g_head + (b*S + q0 + lane + 32)*D + h*DK;
        #pragma unroll
        for (int c4 = 0; c4 < 4; c4++) {
            *reinterpret_cast<float4*>(d0 + c4*4) =
                make_float4(o0[c4*4], o0[c4*4+1], o0[c4*4+2], o0[c4*4+3]);
            *reinterpret_cast<float4*>(d1 + c4*4) =
                make_float4(o1[c4*4], o1[c4*4+1], o1[c4*4+2], o1[c4*4+3]);
        }
    }
}

// ============================================================
// Kernel 4: out = head[B*S,128] @ w_o[128,128]. grid 256, 256 thr.
// ============================================================
__global__ void final_proj_kernel(const float* __restrict__ wo,
                                  float* __restrict__ out) {
    __shared__ float hsT[128][34];
    const int t = threadIdx.x;
    const int row0 = blockIdx.x * 32;

    #pragma unroll
    for (int k = 0; k < 4; k++) {
        int idx = t + k*256;
        int r = idx >> 5, j4 = idx & 31;
        float4 v = *reinterpret_cast<const float4*>(g_head + (row0 + r)*D + j4*4);
        hsT[j4*4+0][r] = v.x; hsT[j4*4+1][r] = v.y;
        hsT[j4*4+2][r] = v.z; hsT[j4*4+3][r] = v.w;
    }
    __syncthreads();

    const int c = t & 127, rh = t >> 7;
    u64 acc[8] = {};
    #pragma unroll 4
    for (int j = 0; j < D; j++) {
        u64 w = dup2(wo[j*D + c]);
        #pragma unroll
        for (int p = 0; p < 8; p++)
            ffma2(acc[p], lds64(&hsT[j][rh*16 + 2*p]), w);
    }
    #pragma unroll
    for (int p = 0; p < 8; p++) {
        float2 v = unpk(acc[p]);
        int r = row0 + rh*16 + 2*p;
        out[r*D + c]     = v.x;
        out[(r+1)*D + c] = v.y;
    }
}

// ============================================================
extern "C" void kernel_launch(void* const* d_in, const int* in_sizes, int n_in,
                              void* d_out, int out_size) {
    const float* x  = (const float*)d_in[0];
    const float* wq = (const float*)d_in[1];
    const float* wk = (const float*)d_in[2];
    const float* wv = (const float*)d_in[3];
    const float* wo = (const float*)d_in[4];
    float* out = (float*)d_out;

    proj_kernel      <<< dim3(Bsz*S/64, 3), 128 >>>(x, wq, wk, wv);
    colsum_kernel    <<< dim3(S/128, BH),   128 >>>();
    attn_kernel      <<< dim3(S/QT, BH),    128 >>>();
    final_proj_kernel<<< Bsz*S/32,          256 >>>(wo, out);
}

// round 5
// speedup vs baseline: 2.7261x; 1.1357x over previous
#include <cuda_runtime.h>
#include <cuda_bf16.h>

#define Bsz 4
#define S   2048
#define D   128
#define H   8
#define DK  16
#define BH  (Bsz*H)

#define QT  64      // q rows per scores/ev CTA
#define MC  128     // m rows staged per chunk
#define NQT (S/QT)  // 32 q-tiles

typedef unsigned long long u64;

// 0.25 * log2(e): folded into Q at projection time so attention uses raw ex2
#define SCQ 0.36067376022224086f

// ---- scratch (no device allocations allowed) ----
__device__ float g_Q[BH*S*DK];                 // pre-scaled by SCQ
__device__ float g_K[BH*S*DK];
__device__ float g_V[BH*S*DK];
__device__ __nv_bfloat16 g_E[(size_t)BH*S*S];  // 256 MB, layout [bh][m][q]
__device__ float g_colpart[NQT*BH*S];          // per-q-tile partial colsums (8 MB)
__device__ float g_colsum[BH*S];
__device__ float g_head[Bsz*S*D];

// ---- packed fp32x2 helpers ----
__device__ __forceinline__ void ffma2(u64& d, u64 a, u64 b){
    asm("fma.rn.f32x2 %0, %1, %2, %0;" : "+l"(d) : "l"(a), "l"(b));
}
__device__ __forceinline__ u64 dup2(float x){
    u64 r; asm("mov.b64 %0, {%1, %1};" : "=l"(r) : "f"(x)); return r;
}
__device__ __forceinline__ float hsum2(u64 v){
    float lo, hi; asm("mov.b64 {%0, %1}, %2;" : "=f"(lo), "=f"(hi) : "l"(v));
    return lo + hi;
}
__device__ __forceinline__ float2 unpk(u64 v){
    float2 r; asm("mov.b64 {%0, %1}, %2;" : "=f"(r.x), "=f"(r.y) : "l"(v));
    return r;
}
__device__ __forceinline__ float ex2f(float x){
    float r; asm("ex2.approx.f32 %0, %1;" : "=f"(r) : "f"(x)); return r;
}
__device__ __forceinline__ u64 lds64(const float* p){
    return *reinterpret_cast<const u64*>(p);
}
__device__ __forceinline__ u64 ldg64(const float* p){
    return *reinterpret_cast<const u64*>(p);
}

// ============================================================
// Kernel 1: Q/K/V projections. grid (B*S/64, 3), 128 threads.
// ============================================================
__global__ void proj_kernel(const float* __restrict__ x,
                            const float* __restrict__ wq,
                            const float* __restrict__ wk,
                            const float* __restrict__ wv) {
    __shared__ float xs[64][132];
    __shared__ float wsT[16][132];
    const int t = threadIdx.x;       // 128
    const int row0 = blockIdx.x * 64;
    const int pj = blockIdx.y;
    const float* W0 = (pj == 0 ? wq : pj == 1 ? wk : wv);
    float* dst = (pj == 0 ? g_Q : pj == 1 ? g_K : g_V);
    const float oscale = (pj == 0) ? SCQ : 1.0f;

    #pragma unroll
    for (int k = 0; k < 16; k++) {
        int idx = t + k*128;
        int r = idx >> 5, q4 = idx & 31;
        *reinterpret_cast<float4*>(&xs[r][q4*4]) =
            *reinterpret_cast<const float4*>(x + (row0 + r)*D + q4*4);
    }

    const int rg = t >> 3, cg = t & 7;
    for (int h = 0; h < H; h++) {
        __syncthreads();
        #pragma unroll
        for (int k = 0; k < 4; k++) {
            int idx = t + k*128;
            int d = idx >> 2, c4 = idx & 3;
            float4 v = *reinterpret_cast<const float4*>(W0 + h*D*DK + d*DK + c4*4);
            wsT[c4*4+0][d] = v.x; wsT[c4*4+1][d] = v.y;
            wsT[c4*4+2][d] = v.z; wsT[c4*4+3][d] = v.w;
        }
        __syncthreads();

        u64 acc[4][2] = {};
        #pragma unroll 8
        for (int d = 0; d < D; d += 2) {
            u64 w0 = lds64(&wsT[cg][d]);
            u64 w1 = lds64(&wsT[cg+8][d]);
            #pragma unroll
            for (int i = 0; i < 4; i++) {
                u64 xv = lds64(&xs[rg*4+i][d]);
                ffma2(acc[i][0], xv, w0);
                ffma2(acc[i][1], xv, w1);
            }
        }
        #pragma unroll
        for (int i = 0; i < 4; i++) {
            int grow = row0 + rg*4 + i;
            int b = grow >> 11, s = grow & (S-1);
            float* o = dst + ((b*H + h)*S + s)*DK;
            o[cg]   = hsum2(acc[i][0]) * oscale;
            o[cg+8] = hsum2(acc[i][1]) * oscale;
        }
    }
}

// ============================================================
// Kernel 2: E[m][q] = ex2(Qhat[q].K[m]) (bf16), plus per-CTA column
// partial sums (sum over this CTA's 64 q rows) -> g_colpart.
// grid (NQT, BH), 128 threads. Lane owns q rows {2*lane, 2*lane+1};
// warps split the 128-m chunk 4 ways; K staged in SMEM.
// ============================================================
__global__ void __launch_bounds__(128) scoresE_kernel() {
    __shared__ float Ks[MC][16];
    const int t    = threadIdx.x;
    const int w    = t >> 5, lane = t & 31;
    const int bh   = blockIdx.y;
    const int q0   = blockIdx.x * QT;
    const float* Qb = g_Q + (bh*S + q0)*DK;
    const float* Kb = g_K + bh*S*DK;
    __nv_bfloat16* Eb = g_E + (size_t)bh*S*S;
    float* cp = g_colpart + blockIdx.x*(BH*S) + bh*S;

    u64 qa[8], qb[8];
    #pragma unroll
    for (int j = 0; j < 8; j++) {
        qa[j] = ldg64(Qb + (2*lane)*DK + 2*j);
        qb[j] = ldg64(Qb + (2*lane+1)*DK + 2*j);
    }

    for (int m0 = 0; m0 < S; m0 += MC) {
        __syncthreads();
        #pragma unroll
        for (int i = 0; i < 4; i++) {
            int idx = t + i*128;                  // 512 float4s
            int r = idx >> 2, c4 = idx & 3;
            *reinterpret_cast<float4*>(&Ks[r][c4*4]) =
                *reinterpret_cast<const float4*>(Kb + (m0 + r)*DK + c4*4);
        }
        __syncthreads();

        const int mbase = w * 32;
        #pragma unroll 4
        for (int mi = 0; mi < 32; mi++) {
            const int m  = mbase + mi;
            const int mg = m0 + m;
            const ulonglong2* kp = reinterpret_cast<const ulonglong2*>(&Ks[m][0]);
            u64 a0 = 0, a1 = 0;
            #pragma unroll
            for (int p = 0; p < 4; p++) {
                ulonglong2 kv = kp[p];            // LDS.128 broadcast
                ffma2(a0, qa[2*p],   kv.x);
                ffma2(a0, qa[2*p+1], kv.y);
                ffma2(a1, qb[2*p],   kv.x);
                ffma2(a1, qb[2*p+1], kv.y);
            }
            float e0 = ex2f(hsum2(a0));
            float e1 = ex2f(hsum2(a1));
            // coalesced 128B/warp bf16x2 store: E[mg][q0+2lane .. +1]
            *reinterpret_cast<__nv_bfloat162*>(Eb + (size_t)mg*S + q0 + 2*lane) =
                __floats2bfloat162_rn(e0, e1);
            // column partial sum over this CTA's 64 q rows
            float cs = e0 + e1;
            #pragma unroll
            for (int off = 16; off; off >>= 1)
                cs += __shfl_xor_sync(0xffffffffu, cs, off);
            if (lane == 0) cp[mg] = cs;
        }
    }
}

// ============================================================
// Kernel 3: colsum = sum over the 32 q-tile partials (deterministic).
// ============================================================
__global__ void colred_kernel() {
    const int i = blockIdx.x*1024 + threadIdx.x;   // [0, BH*S)
    float s = 0.f;
    #pragma unroll
    for (int qt = 0; qt < NQT; qt++) s += g_colpart[qt*(BH*S) + i];
    g_colsum[i] = s;
}

// ============================================================
// Kernel 4: out[q,:] = sum_m E[m][q] * (V[m,:]/colsum[m]).
// grid (NQT, BH), 128 threads. Lane owns q rows {2*lane, 2*lane+1};
// warps split m 4 ways; V' staged in SMEM; E streamed (coalesced LDG.32).
// ============================================================
__global__ void __launch_bounds__(128) ev_kernel() {
    __shared__ float Vs[MC][16];
    __shared__ float red[3][QT][18];
    const int t    = threadIdx.x;
    const int w    = t >> 5, lane = t & 31;
    const int bh   = blockIdx.y;
    const int q0   = blockIdx.x * QT;
    const float* Vb = g_V + bh*S*DK;
    const float* cs = g_colsum + bh*S;
    const __nv_bfloat16* Eb = g_E + (size_t)bh*S*S;

    u64 acc0[8] = {}, acc1[8] = {};

    for (int m0 = 0; m0 < S; m0 += MC) {
        __syncthreads();
        #pragma unroll
        for (int i = 0; i < 4; i++) {
            int idx = t + i*128;                  // 512 float4s
            int r = idx >> 2, c4 = idx & 3;
            float4 v = *reinterpret_cast<const float4*>(Vb + (m0 + r)*DK + c4*4);
            float inv = __frcp_rn(cs[m0 + r]);
            v.x *= inv; v.y *= inv; v.z *= inv; v.w *= inv;
            *reinterpret_cast<float4*>(&Vs[r][c4*4]) = v;
        }
        __syncthreads();

        const int mbase = w * 32;
        #pragma unroll 4
        for (int mi = 0; mi < 32; mi++) {
            const int m  = mbase + mi;
            const int mg = m0 + m;
            __nv_bfloat162 eb = *reinterpret_cast<const __nv_bfloat162*>(
                Eb + (size_t)mg*S + q0 + 2*lane);          // coalesced 128B/warp
            float2 ef = __bfloat1622float2(eb);
            u64 E0 = dup2(ef.x), E1 = dup2(ef.y);
            const ulonglong2* vp = reinterpret_cast<const ulonglong2*>(&Vs[m][0]);
            #pragma unroll
            for (int p = 0; p < 4; p++) {
                ulonglong2 vv = vp[p];            // LDS.128 broadcast
                ffma2(acc0[2*p],   E0, vv.x);
                ffma2(acc0[2*p+1], E0, vv.y);
                ffma2(acc1[2*p],   E1, vv.x);
                ffma2(acc1[2*p+1], E1, vv.y);
            }
        }
    }

    // cross-warp reduction over the 4 m-slices
    __syncthreads();
    if (w) {
        #pragma unroll
        for (int j = 0; j < 8; j++) {
            float2 p0 = unpk(acc0[j]), p1 = unpk(acc1[j]);
            red[w-1][2*lane][2*j]      = p0.x;
            red[w-1][2*lane][2*j+1]    = p0.y;
            red[w-1][2*lane+1][2*j]    = p1.x;
            red[w-1][2*lane+1][2*j+1]  = p1.y;
        }
    }
    __syncthreads();
    if (w == 0) {
        const int b = bh >> 3, h = bh & 7;
        float o0[16], o1[16];
        #pragma unroll
        for (int j = 0; j < 8; j++) {
            float2 p0 = unpk(acc0[j]), p1 = unpk(acc1[j]);
            o0[2*j] = p0.x; o0[2*j+1] = p0.y;
            o1[2*j] = p1.x; o1[2*j+1] = p1.y;
        }
        #pragma unroll
        for (int sl = 0; sl < 3; sl++) {
            #pragma unroll
            for (int c = 0; c < 16; c++) {
                o0[c] += red[sl][2*lane][c];
                o1[c] += red[sl][2*lane+1][c];
            }
        }
        float* d0 = g_head + (b*S + q0 + 2*lane)*D     + h*DK;
        float* d1 = g_head + (b*S + q0 + 2*lane + 1)*D + h*DK;
        #pragma unroll
        for (int c4 = 0; c4 < 4; c4++) {
            *reinterpret_cast<float4*>(d0 + c4*4) =
                make_float4(o0[c4*4], o0[c4*4+1], o0[c4*4+2], o0[c4*4+3]);
            *reinterpret_cast<float4*>(d1 + c4*4) =
                make_float4(o1[c4*4], o1[c4*4+1], o1[c4*4+2], o1[c4*4+3]);
        }
    }
}

// ============================================================
// Kernel 5: out = head[B*S,128] @ w_o[128,128]. grid 256, 256 thr.
// ============================================================
__global__ void final_proj_kernel(const float* __restrict__ wo,
                                  float* __restrict__ out) {
    __shared__ float hsT[128][34];
    const int t = threadIdx.x;
    const int row0 = blockIdx.x * 32;

    #pragma unroll
    for (int k = 0; k < 4; k++) {
        int idx = t + k*256;
        int r = idx >> 5, j4 = idx & 31;
        float4 v = *reinterpret_cast<const float4*>(g_head + (row0 + r)*D + j4*4);
        hsT[j4*4+0][r] = v.x; hsT[j4*4+1][r] = v.y;
        hsT[j4*4+2][r] = v.z; hsT[j4*4+3][r] = v.w;
    }
    __syncthreads();

    const int c = t & 127, rh = t >> 7;
    u64 acc[8] = {};
    #pragma unroll 4
    for (int j = 0; j < D; j++) {
        u64 w = dup2(wo[j*D + c]);
        #pragma unroll
        for (int p = 0; p < 8; p++)
            ffma2(acc[p], lds64(&hsT[j][rh*16 + 2*p]), w);
    }
    #pragma unroll
    for (int p = 0; p < 8; p++) {
        float2 v = unpk(acc[p]);
        int r = row0 + rh*16 + 2*p;
        out[r*D + c]     = v.x;
        out[(r+1)*D + c] = v.y;
    }
}

// ============================================================
extern "C" void kernel_launch(void* const* d_in, const int* in_sizes, int n_in,
                              void* d_out, int out_size) {
    const float* x  = (const float*)d_in[0];
    const float* wq = (const float*)d_in[1];
    const float* wk = (const float*)d_in[2];
    const float* wv = (const float*)d_in[3];
    const float* wo = (const float*)d_in[4];
    float* out = (float*)d_out;

    proj_kernel      <<< dim3(Bsz*S/64, 3), 128 >>>(x, wq, wk, wv);
    scoresE_kernel   <<< dim3(NQT, BH),     128 >>>();
    colred_kernel    <<< BH*S/1024,        1024 >>>();
    ev_kernel        <<< dim3(NQT, BH),     128 >>>();
    final_proj_kernel<<< Bsz*S/32,          256 >>>(wo, out);
}